// round 12
// baseline (speedup 1.0000x reference)
#include <cuda_runtime.h>
#include <math.h>

#define T_TOT 200000
#define EE 500
#define EI 100
#define NB 34
#define NHB 18
#define TNO 50
#define BLK 1024
#define WARM 1024
#define NBLK ((T_TOT + BLK - 1) / BLK)          // 196
#define SMEM_K4P ((256 + 4*4096 + (WARM + BLK)) * 4)
#define M3ROW 66752                              // padded phase-row length
#define PAD3 24
#define XS3 1064                                 // 1024 + 40
#define HB 4                                     // h per block in k2p/kc1
#define CTL 1136                                 // corr tile: 1024 + 112
#define SMEM_K2P (HB*40*36*8 + 4*XS3*4)          // 63104

#define FMA2(acc, a, b) asm("fma.rn.f32x2 %0, %1, %2, %0;" : "+l"(acc) : "l"(a), "l"(b))
#define PK2(d, lo, hi)  asm("mov.b64 %0, {%1, %2};" : "=l"(d) : "f"(lo), "f"(hi))
#define UPK2(lo, hi, d) asm("mov.b64 {%0, %1}, %2;" : "=f"(lo), "=f"(hi) : "l"(d))

// ---------------- device scratch ----------------
__device__ float d_syn[40 * T_TOT];
__device__ float d_out1[20 * T_TOT];
__device__ float d_F3[40 * 3 * M3ROW];
__device__ float d_G3[20 * 3 * M3ROW];
__device__ float d_a[T_TOT];
__device__ float d_L[T_TOT];
__device__ unsigned d_bitsA[T_TOT / 32 + 8];
__device__ unsigned d_bitsB[T_TOT / 32 + 8];
__device__ int   d_se[EE];
__device__ int   d_si[EI];
__device__ float d_Kp[64];
__device__ float d_sKp[64];
__device__ float d_LUTA[256];         // hist lags 1..8
__device__ float d_LUT12[4 * 4096];   // hist lags 9..56
__device__ float d_sLUTA[256];        // spk-filter lags 1..8
__device__ float d_sLUT12[4 * 4096];  // spk-filter lags 9..56
__device__ float d_g[17];             // Gaussian taps, d in [-8,8]
__device__ float d_ck1[20 * 40 * 12]; // clip-correction taps conv1 (6 left + 6 right)
__device__ float d_ck4[20 * 12];      // clip-correction taps conv4
__device__ float d_theta;

__device__ __forceinline__ float gaussf(int d) {
    float dd = (float)d;
    return expf(-dd * dd / 3.0f);
}

// ---------------- K0a: small precompute (indices, Kp, g, LUTA) ----------------
__global__ void k0a(const float* __restrict__ Ce, const float* __restrict__ Ci,
                    const float* __restrict__ Wh, const float* __restrict__ Th,
                    const float* __restrict__ Ws, const float* __restrict__ Tau) {
    int tid = threadIdx.x;
    for (int e = tid; e < EE; e += 256) {
        int best = 0;
        for (int s = 0; s < 20; s++) if (Ce[s * EE + e] > 0.5f) best = s;
        d_se[e] = best;
    }
    for (int e = tid; e < EI; e += 256) {
        int best = 0;
        for (int s = 0; s < 20; s++) if (Ci[s * EI + e] > 0.5f) best = s;
        d_si[e] = best;
    }
    if (tid < 64) {
        float v = 0.f;
        if (tid < TNO) {
            int j = 49 - tid;                       // Kp[k] = hist_kern[49-k]
            for (int b = 0; b < NHB; b++) {
                float dd = (float)(j - 3 * b);
                v += Wh[b] * expf(-dd * dd / 3.0f);
            }
        }
        d_Kp[tid] = v;
    }
    if (tid >= 64 && tid < 128) {
        int j = tid - 64;
        float v = 0.f;
        if (j < TNO) {
            float tau2 = Tau[0] * Tau[0];
            float tt = (float)j / tau2;
            v = tt * expf(-tt) * Ws[0] * Ws[0];     // spk_kern[j] (lag j+1)
        }
        d_sKp[j] = v;
    }
    if (tid >= 128 && tid < 145) {
        float dd = (float)(tid - 128 - 8);
        d_g[tid - 128] = expf(-dd * dd / 3.0f);
    }
    if (tid == 0) d_theta = Th[0];
    __syncthreads();
    if (tid < 256) {
        float s = 0.f, s2 = 0.f;
        for (int b = 0; b < 8; b++) if ((tid >> b) & 1) { s += d_Kp[b]; s2 += d_sKp[b]; }
        d_LUTA[tid] = s;
        d_sLUTA[tid] = s2;
    }
}

// ---------------- K0b: 12-bit LUTs ----------------
__global__ void k0b(void) {
    int idx = blockIdx.x * 256 + threadIdx.x;
    if (idx < 4 * 4096) {
        int tb = idx >> 12, v = idx & 4095;
        float s = 0.f, s2 = 0.f;
        for (int b = 0; b < 12; b++)
            if ((v >> b) & 1) { s += d_Kp[8 + tb * 12 + b]; s2 += d_sKp[8 + tb * 12 + b]; }
        d_LUT12[idx] = s;
        d_sLUT12[idx] = s2;
    }
}

// ---------------- K0c: clip-correction taps ----------------
// layout [.][12]: k<6 -> left, pos t-56+k, j=6-k; k>=6 -> right, pos t+51+(k-6), j=k-5
__global__ void k0c(const float* __restrict__ w1, const float* __restrict__ w4) {
    int idx = blockIdx.x * 256 + threadIdx.x;
    if (idx < 20 * 40 * 12) {
        int k = idx % 12;
        int hs = idx / 12;
        const float* w = w1 + hs * 34;
        float v;
        if (k < 6) {
            int j = 6 - k;
            v = w[0] * gaussf(j);
            if (j <= 5) v += w[1] * gaussf(j + 3);
            if (j <= 2) v += w[2] * gaussf(j + 6);
        } else {
            int j = k - 5;
            v = w[33] * gaussf(j + 1);
            if (j <= 4) v += w[32] * gaussf(j + 4);
            if (j <= 1) v += w[31] * gaussf(j + 7);
        }
        d_ck1[idx] = v;
    } else if (idx < 20 * 40 * 12 + 20 * 12) {
        int i2 = idx - 20 * 40 * 12;
        int k = i2 % 12;
        int h = i2 / 12;
        const float* w = w4 + h * 34;
        float v;
        if (k < 6) {
            int j = 6 - k;
            v = w[0] * gaussf(j);
            if (j <= 5) v += w[1] * gaussf(j + 3);
            if (j <= 2) v += w[2] * gaussf(j + 6);
        } else {
            int j = k - 5;
            v = w[33] * gaussf(j + 1);
            if (j <= 4) v += w[32] * gaussf(j + 4);
            if (j <= 1) v += w[31] * gaussf(j + 7);
        }
        d_ck4[i2] = v;
    }
}

// ---------------- KZ: zero only the pads of F3/G3 ----------------
// front pad [0,24); tail [66624, 66752) covers all read-but-unwritten cells.
__global__ void kz_pads(void) {
    int tid = blockIdx.x * 256 + threadIdx.x;
    const int per = 24 + 128;
    int total = 180 * per;
    for (int i = tid; i < total; i += gridDim.x * 256) {
        int row = i / per, c = i % per;
        int idx = (c < 24) ? c : (66624 + (c - 24));
        if (row < 120) d_F3[(size_t)row * M3ROW + idx] = 0.f;
        else           d_G3[(size_t)(row - 120) * M3ROW + idx] = 0.f;
    }
}

// ---------------- K1: route synapses -> 40 subunit channels ----------------
__global__ void k1_route(const float* __restrict__ Se, const float* __restrict__ Si) {
    __shared__ float sh[40 * 128];
    __shared__ int sse[EE];
    __shared__ int ssi[EI];
    int tid = threadIdx.x;
    int t0 = blockIdx.x * 128;

    for (int i = tid; i < EE; i += 256) sse[i] = d_se[i];
    for (int i = tid; i < EI; i += 256) ssi[i] = d_si[i];
    for (int i = tid; i < 40 * 128; i += 256) sh[i] = 0.f;
    __syncthreads();

    int w = tid >> 5, lane = tid & 31;
    for (int tl = w; tl < 128; tl += 8) {
        int t = t0 + tl;
        if (t < T_TOT) {
            const float4* row4 = (const float4*)(Se + (size_t)t * EE);
            for (int e4 = lane; e4 < EE / 4; e4 += 32) {
                float4 v = row4[e4];
                int e = e4 * 4;
                if (v.x != 0.f) atomicAdd(&sh[sse[e]     * 128 + tl], v.x);
                if (v.y != 0.f) atomicAdd(&sh[sse[e + 1] * 128 + tl], v.y);
                if (v.z != 0.f) atomicAdd(&sh[sse[e + 2] * 128 + tl], v.z);
                if (v.w != 0.f) atomicAdd(&sh[sse[e + 3] * 128 + tl], v.w);
            }
            const float4* rowi4 = (const float4*)(Si + (size_t)t * EI);
            for (int e4 = lane; e4 < EI / 4; e4 += 32) {
                float4 v = rowi4[e4];
                int e = e4 * 4;
                if (v.x != 0.f) atomicAdd(&sh[(20 + ssi[e])     * 128 + tl], v.x);
                if (v.y != 0.f) atomicAdd(&sh[(20 + ssi[e + 1]) * 128 + tl], v.y);
                if (v.z != 0.f) atomicAdd(&sh[(20 + ssi[e + 2]) * 128 + tl], v.z);
                if (v.w != 0.f) atomicAdd(&sh[(20 + ssi[e + 3]) * 128 + tl], v.w);
            }
        }
    }
    __syncthreads();
    for (int i = tid; i < 40 * 128; i += 256) {
        int s = i >> 7, tl = i & 127;
        int t = t0 + tl;
        if (t < T_TOT) d_syn[(size_t)s * T_TOT + t] = sh[i];
    }
}

// ---------------- KF: F = g * syn, written phase-split ----------------
__global__ void kF_smooth(void) {
    __shared__ float tile[1024 + 16];
    __shared__ float gsh[17];
    int tid = threadIdx.x;
    int s = blockIdx.y;
    int u0 = blockIdx.x * 1024 - 8;
    if (tid < 17) gsh[tid] = d_g[tid];
    for (int i = tid; i < 1040; i += 256) {
        int gidx = u0 + i - 8;
        tile[i] = (gidx >= 0 && gidx < T_TOT) ? d_syn[(size_t)s * T_TOT + gidx] : 0.f;
    }
    __syncthreads();
    for (int j = tid; j < 1024; j += 256) {
        int u = u0 + j;
        if (u < 200008) {
            float acc = 0.f;
            #pragma unroll
            for (int d = 0; d < 17; d++) acc += gsh[d] * tile[j + d];
            int r = ((u % 3) + 3) % 3;
            int m = (u - r) / 3;
            d_F3[((size_t)s * 3 + r) * M3ROW + PAD3 + m] = acc;
        }
    }
}

// ---------------- K2': phase conv 40->HB, 36 taps, f32x2 packed (pre-activation) ----------------
__global__ void k2p(const float* __restrict__ w1) {
    extern __shared__ unsigned char sm2[];
    unsigned long long* ksh2 = (unsigned long long*)sm2;            // HB*40*36 pairs
    float* shx = (float*)(sm2 + (size_t)HB * 40 * 36 * 8);          // 4*XS3
    int tid = threadIdx.x;
    int blk = blockIdx.x;
    int h0 = blockIdx.y * HB;
    int r = blockIdx.z;
    for (int i = tid; i < HB * 40 * 36; i += 256) {
        int b = i % 36;
        int hs = i / 36;                  // hh*40 + s
        int hh = hs / 40, s = hs % 40;
        float v = (b < 34) ? w1[((h0 + hh) * 40 + s) * 34 + b] : 0.f;
        unsigned long long p; PK2(p, v, v);
        ksh2[i] = p;
    }
    int j4 = tid * 4;
    unsigned long long a01[HB], a23[HB];
    #pragma unroll
    for (int hh = 0; hh < HB; hh++) { a01[hh] = 0ull; a23[hh] = 0ull; }
    int W0 = blk * 1024 - 8;

    for (int c0 = 0; c0 < 40; c0 += 4) {
        __syncthreads();
        for (int i = tid; i < 4 * XS3; i += 256) {
            int sl = i / XS3, ii = i % XS3;
            int idx = W0 + ii;
            shx[i] = (idx >= 0 && idx < M3ROW)
                     ? d_F3[((size_t)(c0 + sl) * 3 + r) * M3ROW + idx] : 0.f;
        }
        __syncthreads();
        #pragma unroll
        for (int sl = 0; sl < 4; sl++) {
            const float4* xq = reinterpret_cast<const float4*>(shx + sl * XS3 + j4);
            float4 cur = xq[0];
            #pragma unroll
            for (int g = 0; g < 9; g++) {
                float4 nxt = xq[g + 1];
                float w0 = cur.x, w1v = cur.y, w2 = cur.z, w3 = cur.w;
                float w4v = nxt.x, w5 = nxt.y, w6 = nxt.z;
                unsigned long long wp0, wp1, wp2, wp3, wp4, wp5;
                PK2(wp0, w0, w1v); PK2(wp1, w1v, w2); PK2(wp2, w2, w3);
                PK2(wp3, w3, w4v); PK2(wp4, w4v, w5); PK2(wp5, w5, w6);
                #pragma unroll
                for (int hh = 0; hh < HB; hh++) {
                    const unsigned long long* kq =
                        ksh2 + (size_t)(hh * 40 + (c0 + sl)) * 36 + 4 * g;
                    unsigned long long k0 = kq[0], k1 = kq[1], k2 = kq[2], k3 = kq[3];
                    FMA2(a01[hh], k0, wp0); FMA2(a01[hh], k1, wp1);
                    FMA2(a01[hh], k2, wp2); FMA2(a01[hh], k3, wp3);
                    FMA2(a23[hh], k0, wp2); FMA2(a23[hh], k1, wp3);
                    FMA2(a23[hh], k2, wp4); FMA2(a23[hh], k3, wp5);
                }
                cur = nxt;
            }
        }
    }
    #pragma unroll
    for (int hh = 0; hh < HB; hh++) {
        float v0, v1, v2, v3;
        UPK2(v0, v1, a01[hh]);
        UPK2(v2, v3, a23[hh]);
        float vv[4] = {v0, v1, v2, v3};
        #pragma unroll
        for (int i2 = 0; i2 < 4; i2++) {
            int t = 3 * (blk * 1024 + j4 + i2 - 32) + r + 50;
            if (t >= 0 && t < T_TOT)
                d_out1[(size_t)(h0 + hh) * T_TOT + t] = vv[i2];
        }
    }
}

// ---------------- KC1: clip correction conv1 (12 taps, f32x2) + leaky ReLU ----------------
__global__ void kc1(void) {
    __shared__ unsigned long long ksh2c[HB * 40 * 12];
    __shared__ __align__(16) float xt[4 * CTL];
    int tid = threadIdx.x;
    int t0 = blockIdx.x * 1024;
    int h0 = blockIdx.y * HB;
    for (int i = tid; i < HB * 40 * 12; i += 256) {
        int hs = i / 12;                  // hh*40+s
        int hh = hs / 40, s = hs % 40;
        float v = d_ck1[((h0 + hh) * 40 + s) * 12 + (i % 12)];
        unsigned long long p; PK2(p, v, v);
        ksh2c[i] = p;
    }
    int j4 = tid * 4;
    unsigned long long a01[HB], a23[HB];
    #pragma unroll
    for (int hh = 0; hh < HB; hh++) { a01[hh] = 0ull; a23[hh] = 0ull; }

    for (int c0 = 0; c0 < 40; c0 += 4) {
        __syncthreads();
        for (int i = tid; i < 4 * CTL; i += 256) {
            int sl = i / CTL, ii = i % CTL;
            int g = t0 - 56 + ii;
            xt[sl * CTL + ii] = (g >= 0 && g < T_TOT) ? d_syn[(size_t)(c0 + sl) * T_TOT + g] : 0.f;
        }
        __syncthreads();
        #pragma unroll
        for (int sl = 0; sl < 4; sl++) {
            const float4* xl4 = reinterpret_cast<const float4*>(xt + sl * CTL + j4);
            float4 A = xl4[0], B = xl4[1], C = xl4[2];
            float wl[9] = {A.x, A.y, A.z, A.w, B.x, B.y, B.z, B.w, C.x};
            const float4* xr4 = reinterpret_cast<const float4*>(xt + sl * CTL + j4 + 104);
            float4 D = xr4[0], E = xr4[1], F = xr4[2];
            float vr[12] = {D.x, D.y, D.z, D.w, E.x, E.y, E.z, E.w, F.x, F.y, F.z, F.w};
            unsigned long long wlp[8], wrp[8];
            #pragma unroll
            for (int k = 0; k < 8; k++) { PK2(wlp[k], wl[k], wl[k + 1]); }
            #pragma unroll
            for (int k = 0; k < 8; k++) { PK2(wrp[k], vr[3 + k], vr[4 + k]); }
            #pragma unroll
            for (int hh = 0; hh < HB; hh++) {
                const unsigned long long* kq = ksh2c + (size_t)(hh * 40 + (c0 + sl)) * 12;
                #pragma unroll
                for (int k = 0; k < 6; k++) {
                    unsigned long long cl = kq[k], cr = kq[6 + k];
                    FMA2(a01[hh], cl, wlp[k]);
                    FMA2(a23[hh], cl, wlp[k + 2]);
                    FMA2(a01[hh], cr, wrp[k]);
                    FMA2(a23[hh], cr, wrp[k + 2]);
                }
            }
        }
    }
    #pragma unroll
    for (int hh = 0; hh < HB; hh++) {
        float c0v, c1v, c2v, c3v;
        UPK2(c0v, c1v, a01[hh]);
        UPK2(c2v, c3v, a23[hh]);
        float cc[4] = {c0v, c1v, c2v, c3v};
        #pragma unroll
        for (int i2 = 0; i2 < 4; i2++) {
            int t = t0 + j4 + i2;
            if (t < T_TOT) {
                float v = d_out1[(size_t)(h0 + hh) * T_TOT + t] - cc[i2];
                d_out1[(size_t)(h0 + hh) * T_TOT + t] = (v >= 0.f) ? v : 0.01f * v;
            }
        }
    }
}

// ---------------- KG: G = g * out1, phase-split ----------------
__global__ void kG_smooth(void) {
    __shared__ float tile[1024 + 16];
    __shared__ float gsh[17];
    int tid = threadIdx.x;
    int h = blockIdx.y;
    int u0 = blockIdx.x * 1024 - 8;
    if (tid < 17) gsh[tid] = d_g[tid];
    for (int i = tid; i < 1040; i += 256) {
        int gidx = u0 + i - 8;
        tile[i] = (gidx >= 0 && gidx < T_TOT) ? d_out1[(size_t)h * T_TOT + gidx] : 0.f;
    }
    __syncthreads();
    for (int j = tid; j < 1024; j += 256) {
        int u = u0 + j;
        if (u < 200008) {
            float acc = 0.f;
            #pragma unroll
            for (int d = 0; d < 17; d++) acc += gsh[d] * tile[j + d];
            int r = ((u % 3) + 3) % 3;
            int m = (u - r) / 3;
            d_G3[((size_t)h * 3 + r) * M3ROW + PAD3 + m] = acc;
        }
    }
}

// ---------------- K3': phase conv 20->1 (raw w4) -> a_pre ----------------
__global__ void k3p(const float* __restrict__ w4) {
    __shared__ __align__(16) float ksh[20 * 36];
    __shared__ __align__(16) float shx[4 * XS3];
    int tid = threadIdx.x;
    int blk = blockIdx.x;
    int r = blockIdx.y;
    for (int i = tid; i < 20 * 36; i += 256) {
        int h = i / 36, b = i % 36;
        ksh[i] = (b < 34) ? w4[h * 34 + b] : 0.f;
    }
    int j4 = tid * 4;
    float acc[4] = {0.f, 0.f, 0.f, 0.f};
    int W0 = blk * 1024 - 8;

    for (int c0 = 0; c0 < 20; c0 += 4) {
        __syncthreads();
        for (int i = tid; i < 4 * XS3; i += 256) {
            int sl = i / XS3, ii = i % XS3;
            int idx = W0 + ii;
            shx[i] = (idx >= 0 && idx < M3ROW)
                     ? d_G3[((size_t)(c0 + sl) * 3 + r) * M3ROW + idx] : 0.f;
        }
        __syncthreads();
        #pragma unroll
        for (int sl = 0; sl < 4; sl++) {
            const float4* xq = reinterpret_cast<const float4*>(shx + sl * XS3 + j4);
            const float4* kq = reinterpret_cast<const float4*>(ksh + (size_t)(c0 + sl) * 36);
            float4 cur = xq[0];
            #pragma unroll
            for (int g = 0; g < 9; g++) {
                float4 nxt = xq[g + 1];
                float4 kv = kq[g];
                float w[8] = {cur.x, cur.y, cur.z, cur.w, nxt.x, nxt.y, nxt.z, nxt.w};
                float kk[4] = {kv.x, kv.y, kv.z, kv.w};
                #pragma unroll
                for (int jj = 0; jj < 4; jj++)
                    #pragma unroll
                    for (int i2 = 0; i2 < 4; i2++)
                        acc[i2] += kk[jj] * w[jj + i2];
                cur = nxt;
            }
        }
    }
    float th = d_theta;
    #pragma unroll
    for (int i2 = 0; i2 < 4; i2++) {
        int t = 3 * (blk * 1024 + j4 + i2 - 32) + r + 50;
        if (t >= 0 && t < T_TOT) d_a[t] = acc[i2] + th;
    }
}

// ---------------- KA4: clip correction for conv4 (12 taps), final a and L ----------------
__global__ void ka4(const float* __restrict__ u) {
    __shared__ float ksh[20 * 12];
    __shared__ __align__(16) float xt[4 * CTL];
    int tid = threadIdx.x;
    int t0 = blockIdx.x * 1024;
    for (int i = tid; i < 20 * 12; i += 256) ksh[i] = d_ck4[i];
    int j4 = tid * 4;
    float acc[4] = {0.f, 0.f, 0.f, 0.f};

    for (int c0 = 0; c0 < 20; c0 += 4) {
        __syncthreads();
        for (int i = tid; i < 4 * CTL; i += 256) {
            int sl = i / CTL, ii = i % CTL;
            int g = t0 - 56 + ii;
            xt[sl * CTL + ii] = (g >= 0 && g < T_TOT) ? d_out1[(size_t)(c0 + sl) * T_TOT + g] : 0.f;
        }
        __syncthreads();
        #pragma unroll
        for (int sl = 0; sl < 4; sl++) {
            const float4* xl4 = reinterpret_cast<const float4*>(xt + sl * CTL + j4);
            float4 A = xl4[0], B = xl4[1], C = xl4[2];
            float wl[9] = {A.x, A.y, A.z, A.w, B.x, B.y, B.z, B.w, C.x};
            const float4* xr4 = reinterpret_cast<const float4*>(xt + sl * CTL + j4 + 104);
            float4 D = xr4[0], E = xr4[1], F = xr4[2];
            float vr[12] = {D.x, D.y, D.z, D.w, E.x, E.y, E.z, E.w, F.x, F.y, F.z, F.w};
            const float* kp = ksh + (size_t)(c0 + sl) * 12;
            #pragma unroll
            for (int k = 0; k < 6; k++) {
                float cl = kp[k], cr = kp[6 + k];
                #pragma unroll
                for (int i2 = 0; i2 < 4; i2++) {
                    acc[i2] += cl * wl[k + i2];
                    acc[i2] += cr * vr[3 + k + i2];
                }
            }
        }
    }
    #pragma unroll
    for (int i2 = 0; i2 < 4; i2++) {
        int t = t0 + j4 + i2;
        if (t < T_TOT) {
            float a = d_a[t] - acc[i2];
            d_a[t] = a;
            double uu = (double)u[t];
            double Ld = log(uu) - log1p(-uu);       // logit(u)
            d_L[t] = (float)(Ld - (double)a);
        }
    }
}

// ---------------- K4: block-parallel scan with coalescence warm-up ----------------
__global__ void k4_par(const unsigned* __restrict__ bin,
                       unsigned* __restrict__ bout, int passA) {
    extern __shared__ float smem[];
    float* lutA = smem;                 // 256
    float* lutB = smem + 256;           // 4096 (bits 8..19)
    float* lutC = smem + 256 + 4096;    // bits 20..31
    float* lutD = smem + 256 + 8192;    // bits 32..43
    float* lutE = smem + 256 + 12288;   // bits 44..55
    float* Ls   = smem + 256 + 16384;   // up to WARM + BLK
    int tid = threadIdx.x;
    int bid = blockIdx.x;
    int t0 = bid * BLK;
    int tend = t0 + BLK; if (tend > T_TOT) tend = T_TOT;
    int warm = passA ? ((t0 < WARM) ? t0 : WARM) : 0;
    int tbeg = t0 - warm;
    int n = tend - tbeg;

    for (int i = tid; i < 256; i += 32) lutA[i] = d_LUTA[i];
    for (int i = tid; i < 4096; i += 32) {
        lutB[i] = d_LUT12[i];
        lutC[i] = d_LUT12[4096 + i];
        lutD[i] = d_LUT12[8192 + i];
        lutE[i] = d_LUT12[12288 + i];
    }
    for (int i = tid; i < n; i += 32) Ls[i] = d_L[tbeg + i];
    __syncthreads();
    if (tid != 0) return;

    unsigned long long hist = 0ull;
    if (!passA && t0 > 0) {
        int J = t0 >> 5;
        hist = (unsigned long long)bin[J - 1] | ((unsigned long long)bin[J - 2] << 32);
    }
    int skip = t0 - tbeg;
    #pragma unroll 4
    for (int i = 0; i < n; i++) {
        unsigned b   = (unsigned)hist;
        unsigned h32 = (unsigned)(hist >> 32);
        float rest = (lutA[b & 255u] + lutB[(b >> 8) & 4095u])
                   + (lutC[(b >> 20) & 4095u]
                   + (lutD[h32 & 4095u] + lutE[(h32 >> 12) & 4095u]));
        float dd = Ls[i] - rest;                    // = L - h
        unsigned s = __float_as_uint(dd) >> 31;     // spike iff L < h
        hist = (hist << 1) | (unsigned long long)s;
        int t = tbeg + i;
        if ((t & 31) == 31 && i >= skip) bout[t >> 5] = (unsigned)hist;
    }
}

// ---------------- K5: prob_out + spk_filt (both via LUTs on packed bits) ----------------
__global__ void k5_out(float* __restrict__ out) {
    int t = blockIdx.x * 256 + threadIdx.x;
    if (t >= T_TOT) return;
    int j0 = (t - 1) >> 5;
    unsigned p = 31u - ((unsigned)(t - 1) & 31u);
    unsigned w0 = (j0 >= 0) ? __ldg(&d_bitsB[j0]) : 0u;
    unsigned w1 = (j0 >= 1) ? __ldg(&d_bitsB[j0 - 1]) : 0u;
    unsigned w2 = (j0 >= 2) ? __ldg(&d_bitsB[j0 - 2]) : 0u;
    unsigned long long q = (unsigned long long)w0 | ((unsigned long long)w1 << 32);
    unsigned long long hist = q >> p;
    if (p) hist |= ((unsigned long long)w2) << (64u - p);
    unsigned b   = (unsigned)hist;
    unsigned h32 = (unsigned)(hist >> 32);
    unsigned iB = (b >> 8) & 4095u, iC = (b >> 20) & 4095u;
    unsigned iD = h32 & 4095u, iE = (h32 >> 12) & 4095u;
    float h = __ldg(&d_LUTA[b & 255u])
            + __ldg(&d_LUT12[iB]) + __ldg(&d_LUT12[4096 + iC])
            + __ldg(&d_LUT12[8192 + iD]) + __ldg(&d_LUT12[12288 + iE]);
    float spk = __ldg(&d_sLUTA[b & 255u])
              + __ldg(&d_sLUT12[iB]) + __ldg(&d_sLUT12[4096 + iC])
              + __ldg(&d_sLUT12[8192 + iD]) + __ldg(&d_sLUT12[12288 + iE]);
    float x = d_a[t] + h;
    out[t] = spk;
    out[T_TOT + t] = 1.f / (1.f + expf(-x));
}

extern "C" void kernel_launch(void* const* d_in, const int* in_sizes, int n_in,
                              void* d_out, int out_size) {
    const float* Se  = (const float*)d_in[0];
    const float* Si  = (const float*)d_in[1];
    const float* Ce  = (const float*)d_in[2];
    const float* Ci  = (const float*)d_in[3];
    const float* w1  = (const float*)d_in[4];
    const float* w4  = (const float*)d_in[5];
    const float* Wh  = (const float*)d_in[6];
    const float* Th  = (const float*)d_in[7];
    const float* Ws  = (const float*)d_in[8];
    const float* Tau = (const float*)d_in[9];
    const float* u   = (const float*)d_in[10];
    float* out = (float*)d_out;

    cudaFuncSetAttribute(k4_par, cudaFuncAttributeMaxDynamicSharedMemorySize, SMEM_K4P);
    cudaFuncSetAttribute(k2p, cudaFuncAttributeMaxDynamicSharedMemorySize, SMEM_K2P);

    unsigned* bitsA; cudaGetSymbolAddress((void**)&bitsA, d_bitsA);
    unsigned* bitsB; cudaGetSymbolAddress((void**)&bitsB, d_bitsB);

    k0a<<<1, 256>>>(Ce, Ci, Wh, Th, Ws, Tau);
    k0b<<<64, 256>>>();
    k0c<<<40, 256>>>(w1, w4);
    kz_pads<<<32, 256>>>();
    k1_route<<<(T_TOT + 127) / 128, 256>>>(Se, Si);
    kF_smooth<<<dim3(196, 40), 256>>>();
    k2p<<<dim3(66, 5, 3), 256, SMEM_K2P>>>(w1);
    kc1<<<dim3(196, 5), 256>>>();
    kG_smooth<<<dim3(196, 20), 256>>>();
    k3p<<<dim3(66, 3), 256>>>(w4);
    ka4<<<196, 256>>>(u);
    k4_par<<<NBLK, 32, SMEM_K4P>>>(bitsB, bitsA, 1);   // pass A
    k4_par<<<NBLK, 32, SMEM_K4P>>>(bitsA, bitsB, 0);   // pass B (exact boundaries)
    k5_out<<<(T_TOT + 255) / 256, 256>>>(out);
}